// round 2
// baseline (speedup 1.0000x reference)
#include <cuda_runtime.h>

// Per-row L2 normalization: out[r, :] = in[r, :] * rsqrt(sum(in[r, :]^2))
// Shapes: 16384 rows x 4096 cols, fp32.
// One CTA per row, 256 threads, 4x float4 per thread held in registers
// (single HBM read of the input).

#define ROWS 16384
#define COLS 4096
#define VEC_PER_ROW (COLS / 4)     // 1024 float4
#define THREADS 256
#define VEC_PER_THREAD (VEC_PER_ROW / THREADS)  // 4

__global__ __launch_bounds__(THREADS, 8)
void l2norm_row_kernel(const float4* __restrict__ in, float4* __restrict__ out) {
    const int row = blockIdx.x;
    const size_t base = (size_t)row * VEC_PER_ROW;
    const int t = threadIdx.x;

    // Front-batched loads: 4 independent LDG.128, values stay in registers.
    float4 v[VEC_PER_THREAD];
#pragma unroll
    for (int i = 0; i < VEC_PER_THREAD; i++) {
        v[i] = in[base + t + i * THREADS];
    }

    // Per-thread sum of squares.
    float ss = 0.0f;
#pragma unroll
    for (int i = 0; i < VEC_PER_THREAD; i++) {
        ss = fmaf(v[i].x, v[i].x, ss);
        ss = fmaf(v[i].y, v[i].y, ss);
        ss = fmaf(v[i].z, v[i].z, ss);
        ss = fmaf(v[i].w, v[i].w, ss);
    }

    // Warp reduce.
#pragma unroll
    for (int o = 16; o > 0; o >>= 1) {
        ss += __shfl_xor_sync(0xffffffffu, ss, o);
    }

    // Cross-warp reduce via smem (8 warps).
    __shared__ float warp_sum[THREADS / 32];
    if ((t & 31) == 0) warp_sum[t >> 5] = ss;
    __syncthreads();

    float tot = 0.0f;
#pragma unroll
    for (int w = 0; w < THREADS / 32; w++) tot += warp_sum[w];

    const float inv = rsqrtf(tot);

    // Scale and store.
#pragma unroll
    for (int i = 0; i < VEC_PER_THREAD; i++) {
        float4 o4;
        o4.x = v[i].x * inv;
        o4.y = v[i].y * inv;
        o4.z = v[i].z * inv;
        o4.w = v[i].w * inv;
        out[base + t + i * THREADS] = o4;
    }
}

extern "C" void kernel_launch(void* const* d_in, const int* in_sizes, int n_in,
                              void* d_out, int out_size) {
    const float4* in = (const float4*)d_in[0];
    float4* out = (float4*)d_out;
    l2norm_row_kernel<<<ROWS, THREADS>>>(in, out);
}

// round 3
// speedup vs baseline: 1.0086x; 1.0086x over previous
#include <cuda_runtime.h>

// Per-row L2 normalization: out[r, :] = in[r, :] * rsqrt(sum(in[r, :]^2))
// 16384 rows x 4096 cols fp32. One CTA per row, 256 threads, 4x float4 per
// thread held in registers (single HBM read), streaming cache hints (.cs)
// on both the load and store paths since neither stream is ever reused.

#define ROWS 16384
#define COLS 4096
#define VEC_PER_ROW (COLS / 4)     // 1024 float4
#define THREADS 256
#define VEC_PER_THREAD (VEC_PER_ROW / THREADS)  // 4

__global__ __launch_bounds__(THREADS, 8)
void l2norm_row_kernel(const float4* __restrict__ in, float4* __restrict__ out) {
    const int row = blockIdx.x;
    const size_t base = (size_t)row * VEC_PER_ROW;
    const int t = threadIdx.x;

    // Front-batched streaming loads: 4 independent LDG.128.CS.
    float4 v[VEC_PER_THREAD];
#pragma unroll
    for (int i = 0; i < VEC_PER_THREAD; i++) {
        v[i] = __ldcs(&in[base + t + i * THREADS]);
    }

    // Per-thread sum of squares.
    float ss = 0.0f;
#pragma unroll
    for (int i = 0; i < VEC_PER_THREAD; i++) {
        ss = fmaf(v[i].x, v[i].x, ss);
        ss = fmaf(v[i].y, v[i].y, ss);
        ss = fmaf(v[i].z, v[i].z, ss);
        ss = fmaf(v[i].w, v[i].w, ss);
    }

    // Warp reduce.
#pragma unroll
    for (int o = 16; o > 0; o >>= 1) {
        ss += __shfl_xor_sync(0xffffffffu, ss, o);
    }

    // Cross-warp reduce via smem (8 warps).
    __shared__ float warp_sum[THREADS / 32];
    if ((t & 31) == 0) warp_sum[t >> 5] = ss;
    __syncthreads();

    float tot = 0.0f;
#pragma unroll
    for (int w = 0; w < THREADS / 32; w++) tot += warp_sum[w];

    const float inv = rsqrtf(tot);

    // Scale and store with evict-first hint (no reuse of output).
#pragma unroll
    for (int i = 0; i < VEC_PER_THREAD; i++) {
        float4 o4;
        o4.x = v[i].x * inv;
        o4.y = v[i].y * inv;
        o4.z = v[i].z * inv;
        o4.w = v[i].w * inv;
        __stcs(&out[base + t + i * THREADS], o4);
    }
}

extern "C" void kernel_launch(void* const* d_in, const int* in_sizes, int n_in,
                              void* d_out, int out_size) {
    const float4* in = (const float4*)d_in[0];
    float4* out = (float4*)d_out;
    l2norm_row_kernel<<<ROWS, THREADS>>>(in, out);
}

// round 4
// speedup vs baseline: 1.0303x; 1.0215x over previous
#include <cuda_runtime.h>

// Per-row L2 normalization: out[r, :] = in[r, :] * rsqrt(sum(in[r, :]^2))
// 16384 rows x 4096 cols fp32. One CTA per row, 512 threads, 2x float4 per
// thread in registers (single HBM read), streaming (.cs) loads and stores.
// Shape chosen to keep oe*MLP_p1 = 4*2 = 8 below the L1tex-queue contention
// threshold (Q_th~16) to minimize cross-CTA completion spread.

#define ROWS 16384
#define COLS 4096
#define VEC_PER_ROW (COLS / 4)     // 1024 float4
#define THREADS 512
#define VEC_PER_THREAD (VEC_PER_ROW / THREADS)  // 2
#define NWARPS (THREADS / 32)      // 16

__global__ __launch_bounds__(THREADS, 4)
void l2norm_row_kernel(const float4* __restrict__ in, float4* __restrict__ out) {
    const int row = blockIdx.x;
    const size_t base = (size_t)row * VEC_PER_ROW;
    const int t = threadIdx.x;

    // Front-batched streaming loads: 2 independent LDG.128.CS.
    float4 v[VEC_PER_THREAD];
#pragma unroll
    for (int i = 0; i < VEC_PER_THREAD; i++) {
        v[i] = __ldcs(&in[base + t + i * THREADS]);
    }

    // Per-thread sum of squares.
    float ss = 0.0f;
#pragma unroll
    for (int i = 0; i < VEC_PER_THREAD; i++) {
        ss = fmaf(v[i].x, v[i].x, ss);
        ss = fmaf(v[i].y, v[i].y, ss);
        ss = fmaf(v[i].z, v[i].z, ss);
        ss = fmaf(v[i].w, v[i].w, ss);
    }

    // Warp reduce.
#pragma unroll
    for (int o = 16; o > 0; o >>= 1) {
        ss += __shfl_xor_sync(0xffffffffu, ss, o);
    }

    // Cross-warp reduce via smem (16 warps).
    __shared__ float warp_sum[NWARPS];
    if ((t & 31) == 0) warp_sum[t >> 5] = ss;
    __syncthreads();

    float tot = 0.0f;
#pragma unroll
    for (int w = 0; w < NWARPS; w++) tot += warp_sum[w];

    const float inv = rsqrtf(tot);

    // Scale and store with evict-first hint (no reuse of output).
#pragma unroll
    for (int i = 0; i < VEC_PER_THREAD; i++) {
        float4 o4;
        o4.x = v[i].x * inv;
        o4.y = v[i].y * inv;
        o4.z = v[i].z * inv;
        o4.w = v[i].w * inv;
        __stcs(&out[base + t + i * THREADS], o4);
    }
}

extern "C" void kernel_launch(void* const* d_in, const int* in_sizes, int n_in,
                              void* d_out, int out_size) {
    const float4* in = (const float4*)d_in[0];
    float4* out = (float4*)d_out;
    l2norm_row_kernel<<<ROWS, THREADS>>>(in, out);
}